// round 1
// baseline (speedup 1.0000x reference)
#include <cuda_runtime.h>

// ---------------------------------------------------------------------------
// ModalityRouter: logits = x @ gate_w^T ; top-2 ; softmax ; expert load
//   x:      [4, 8192, 2048] fp32  -> 32768 tokens x 2048
//   gate_w: [64, 2048] fp32
// Output (fp32, concatenated):
//   gates [32768*2] | top_indices [32768*2] | load [64] | top_logits [32768*2]
// ---------------------------------------------------------------------------

#define Dk        2048
#define NE        64
#define NTOK      32768
#define BM        128
#define BK        32
#define NTHREADS  256
#define XS_STRIDE 130      // floats per k-row of x tile (BM + 2, keeps u64 reads aligned)
#define WS_STRIDE 65       // floats per k-row of w tile (NE + 1)
#define LG_STRIDE 65       // logits row stride (conflict-free column scan)

typedef unsigned long long u64;

// pack (v, v) into an f32x2 register pair
__device__ __forceinline__ u64 pk2(float v) {
    u64 r;
    unsigned int b = __float_as_uint(v);
    asm("mov.b64 %0, {%1, %2};" : "=l"(r) : "r"(b), "r"(b));
    return r;
}

// packed dual fp32 FMA (sm_100+): d.lo += a.lo*b.lo ; d.hi += a.hi*b.hi
__device__ __forceinline__ void fma2(u64 &d, u64 a, u64 b) {
    asm("fma.rn.f32x2 %0, %1, %2, %0;" : "+l"(d) : "l"(a), "l"(b));
}

__global__ void zero_load_kernel(float* __restrict__ p) {
    p[threadIdx.x] = 0.0f;
}

__device__ __forceinline__ void store_tile(float* xs, float* ws,
                                           const float4* xv, const float4* wv,
                                           int lr, int lc4) {
#pragma unroll
    for (int p = 0; p < 4; p++) {
        int t = lr + 32 * p;
        xs[(lc4 + 0) * XS_STRIDE + t] = xv[p].x;
        xs[(lc4 + 1) * XS_STRIDE + t] = xv[p].y;
        xs[(lc4 + 2) * XS_STRIDE + t] = xv[p].z;
        xs[(lc4 + 3) * XS_STRIDE + t] = xv[p].w;
    }
#pragma unroll
    for (int p = 0; p < 2; p++) {
        int e = lr + 32 * p;
        ws[(lc4 + 0) * WS_STRIDE + e] = wv[p].x;
        ws[(lc4 + 1) * WS_STRIDE + e] = wv[p].y;
        ws[(lc4 + 2) * WS_STRIDE + e] = wv[p].z;
        ws[(lc4 + 3) * WS_STRIDE + e] = wv[p].w;
    }
}

__device__ __forceinline__ void load_tile(const float* __restrict__ x,
                                          const float* __restrict__ w,
                                          float4* xv, float4* wv,
                                          int tok0, int kt, int lr, int lc4) {
#pragma unroll
    for (int p = 0; p < 4; p++)
        xv[p] = *reinterpret_cast<const float4*>(
            x + (size_t)(tok0 + lr + 32 * p) * Dk + kt + lc4);
#pragma unroll
    for (int p = 0; p < 2; p++)
        wv[p] = *reinterpret_cast<const float4*>(
            w + (size_t)(lr + 32 * p) * Dk + kt + lc4);
}

__global__ void __launch_bounds__(NTHREADS, 2)
router_kernel(const float* __restrict__ x, const float* __restrict__ w,
              float* __restrict__ out)
{
    // one buffer, two lives: [xs | ws] during GEMM, logits[BM][LG_STRIDE] after
    __shared__ __align__(16) unsigned char smem_raw[BM * LG_STRIDE * 4]; // 33280 B
    __shared__ float sg[2 * BM];
    __shared__ int   si[2 * BM];

    float* xs  = reinterpret_cast<float*>(smem_raw);                       // [BK][XS_STRIDE]
    float* ws  = reinterpret_cast<float*>(smem_raw + BK * XS_STRIDE * 4);  // [BK][WS_STRIDE]
    float* lg  = reinterpret_cast<float*>(smem_raw);                       // [BM][LG_STRIDE]
    u64*   xs2 = reinterpret_cast<u64*>(smem_raw);                         // token-pair view

    const int tid  = threadIdx.x;
    const int tx   = tid & 15;   // expert group: experts tx*4 .. tx*4+3
    const int ty   = tid >> 4;   // token group:  tokens ty*8 .. ty*8+7
    const int tok0 = blockIdx.x * BM;
    const int lr   = tid >> 3;        // load row-group (0..31)
    const int lc4  = (tid & 7) * 4;   // load k-offset within tile

    u64 acc[16];                 // [token-pair i][expert j] f32x2 accumulators
#pragma unroll
    for (int i = 0; i < 16; i++) acc[i] = 0ull;

    float4 xv[4], wv[2];

    // prologue: tile 0 -> smem
    load_tile(x, w, xv, wv, tok0, 0, lr, lc4);
    store_tile(xs, ws, xv, wv, lr, lc4);
    __syncthreads();

    for (int kt = 0; kt < Dk; kt += BK) {
        const bool has_next = (kt + BK) < Dk;
        if (has_next)
            load_tile(x, w, xv, wv, tok0, kt + BK, lr, lc4);   // prefetch into regs

#pragma unroll 4
        for (int k = 0; k < BK; k++) {
            const int ab = k * (XS_STRIDE / 2) + ty * 4;       // u64 index
            u64 a0 = xs2[ab + 0];
            u64 a1 = xs2[ab + 1];
            u64 a2 = xs2[ab + 2];
            u64 a3 = xs2[ab + 3];
            const int bb = k * WS_STRIDE + tx * 4;
            u64 B0 = pk2(ws[bb + 0]);
            u64 B1 = pk2(ws[bb + 1]);
            u64 B2 = pk2(ws[bb + 2]);
            u64 B3 = pk2(ws[bb + 3]);
            fma2(acc[ 0], a0, B0); fma2(acc[ 1], a0, B1); fma2(acc[ 2], a0, B2); fma2(acc[ 3], a0, B3);
            fma2(acc[ 4], a1, B0); fma2(acc[ 5], a1, B1); fma2(acc[ 6], a1, B2); fma2(acc[ 7], a1, B3);
            fma2(acc[ 8], a2, B0); fma2(acc[ 9], a2, B1); fma2(acc[10], a2, B2); fma2(acc[11], a2, B3);
            fma2(acc[12], a3, B0); fma2(acc[13], a3, B1); fma2(acc[14], a3, B2); fma2(acc[15], a3, B3);
        }
        __syncthreads();
        if (has_next) {
            store_tile(xs, ws, xv, wv, lr, lc4);
            __syncthreads();
        }
    }

    // ---- epilogue: logits -> smem (overwrites xs/ws; all reads fenced above)
#pragma unroll
    for (int i = 0; i < 4; i++) {
#pragma unroll
        for (int j = 0; j < 4; j++) {
            union { u64 u; float f[2]; } c;
            c.u = acc[i * 4 + j];
            const int t = ty * 8 + 2 * i;
            const int e = tx * 4 + j;
            lg[(t    ) * LG_STRIDE + e] = c.f[0];
            lg[(t + 1) * LG_STRIDE + e] = c.f[1];
        }
    }
    __syncthreads();

    float* out_gates = out;
    float* out_idx   = out + 2 * NTOK;
    float* out_load  = out + 4 * NTOK;
    float* out_tlog  = out + 4 * NTOK + NE;

    if (tid < BM) {
        const float* row = lg + tid * LG_STRIDE;
        // jax.lax.top_k tie-break: lowest index first -> strict '>' on ascending scan
        float m1 = -1e30f, m2 = -1e30f;
        int   i1 = 0,      i2 = 0;
        for (int e = 0; e < NE; e++) {
            float v = row[e];
            if (v > m1)      { m2 = m1; i2 = i1; m1 = v; i1 = e; }
            else if (v > m2) { m2 = v;  i2 = e; }
        }
        // softmax over [m1, m2] (m1 >= m2): stable form
        float ex  = expf(m2 - m1);
        float inv = 1.0f / (1.0f + ex);
        float g1  = inv;
        float g2  = ex * inv;

        const int t = tok0 + tid;
        reinterpret_cast<float2*>(out_gates)[t] = make_float2(g1, g2);
        reinterpret_cast<float2*>(out_idx)[t]   = make_float2((float)i1, (float)i2);
        reinterpret_cast<float2*>(out_tlog)[t]  = make_float2(m1, m2);

        sg[2 * tid]     = g1;  sg[2 * tid + 1] = g2;
        si[2 * tid]     = i1;  si[2 * tid + 1] = i2;
    }
    __syncthreads();

    // per-CTA deterministic expert-load partial, one atomic per expert per CTA
    if (tid < NE) {
        float s = 0.0f;
#pragma unroll 8
        for (int n = 0; n < 2 * BM; n++)
            s += (si[n] == tid) ? sg[n] : 0.0f;
        atomicAdd(out_load + tid, s);
    }
}

extern "C" void kernel_launch(void* const* d_in, const int* in_sizes, int n_in,
                              void* d_out, int out_size) {
    const float* x = (const float*)d_in[0];   // [4*8192, 2048]
    const float* w = (const float*)d_in[1];   // [64, 2048]
    float* out = (float*)d_out;

    // d_out is poisoned: zero the load region before atomics
    zero_load_kernel<<<1, NE>>>(out + 4 * NTOK);
    router_kernel<<<NTOK / BM, NTHREADS>>>(x, w, out);
}

// round 3
// speedup vs baseline: 1.3002x; 1.3002x over previous
#include <cuda_runtime.h>
#include <cstdint>

// ---------------------------------------------------------------------------
// ModalityRouter via mma.sync (m16n8k8 tf32) with 3-product fp32 split
//   logits = x @ gate_w^T ; top-2 ; softmax ; expert load
//   x: [32768, 2048] fp32   gate_w: [64, 2048] fp32
// Output fp32: gates[65536] | idx[65536] | load[64] | top_logits[65536]
// ---------------------------------------------------------------------------

#define DK        2048
#define NE        64
#define NTOK      32768
#define BM        128
#define NTHREADS  256
#define NGROUPS   (DK / 16)      // 128 groups of 16 k-columns

// precomputed tf32-split of gate_w (hi/lo), written by prep_kernel each call
__device__ float g_Bhi[NE * DK];
__device__ float g_Blo[NE * DK];

__device__ __forceinline__ float tf32_trunc(float v) {
    return __uint_as_float(__float_as_uint(v) & 0xFFFFE000u);
}

__global__ void prep_kernel(const float* __restrict__ w) {
    int i = blockIdx.x * 256 + threadIdx.x;       // grid covers NE*DK exactly
    float v  = w[i];
    float hi = tf32_trunc(v);
    float lo = tf32_trunc(v - hi);                // v-hi exact; re-trunc to tf32
    g_Bhi[i] = hi;
    g_Blo[i] = lo;
}

__global__ void zero_load_kernel(float* __restrict__ p) { p[threadIdx.x] = 0.0f; }

// warp-level tensor op: D += A(hi/lo tf32) * B(tf32)
__device__ __forceinline__ void mma8(float* d, const uint32_t* a,
                                     uint32_t b0, uint32_t b1) {
    asm volatile(
        "mma.sync.aligned.m16n8k8.row.col.f32.tf32.tf32.f32 "
        "{%0,%1,%2,%3}, {%4,%5,%6,%7}, {%8,%9}, {%0,%1,%2,%3};"
        : "+f"(d[0]), "+f"(d[1]), "+f"(d[2]), "+f"(d[3])
        : "r"(a[0]), "r"(a[1]), "r"(a[2]), "r"(a[3]), "r"(b0), "r"(b1));
}

union F4 { float4 v; float f[4]; uint32_t u[4]; };

// ---------------------------------------------------------------------------
__global__ void __launch_bounds__(NTHREADS, 2)
router_kernel(const float* __restrict__ x, float* __restrict__ out)
{
    __shared__ float lg[BM][NE + 1];
    __shared__ float sg[2 * BM];
    __shared__ int   si[2 * BM];

    const int tid    = threadIdx.x;
    const int wid    = tid >> 5;
    const int lane   = tid & 31;
    const int gid    = lane >> 2;       // fragment row/col group (0..7)
    const int tig    = lane & 3;        // thread-in-group (0..3)
    const int tslice = wid >> 1;        // token slice (0..3): 32 tokens each
    const int eslice = wid & 1;         // expert slice (0..1): 32 experts each
    const int tok0   = blockIdx.x * BM;

    // A: rows tok0 + tslice*32 + {gid, gid+8, gid+16, gid+24}
    const float* xp = x + (size_t)(tok0 + tslice * 32 + gid) * DK + tig * 4;
    // B: rows (experts) eslice*32 + nt*8 + gid
    const size_t boff = (size_t)(eslice * 32 + gid) * DK + tig * 4;
    const float* bhp = g_Bhi + boff;
    const float* blp = g_Blo + boff;

    float acc[2][4][4];
#pragma unroll
    for (int mt = 0; mt < 2; mt++)
#pragma unroll
        for (int nt = 0; nt < 4; nt++)
#pragma unroll
            for (int q = 0; q < 4; q++) acc[mt][nt][q] = 0.0f;

    for (int g = 0; g < NGROUPS; ++g) {
        const int kt = g * 16;

        // ---- loads: A raw fp32 fragments + B precomputed hi/lo ----
        F4 ar[2][2];  // [m-tile][row-half]
        ar[0][0].v = *reinterpret_cast<const float4*>(xp + kt);
        ar[0][1].v = *reinterpret_cast<const float4*>(xp + 8 * DK + kt);
        ar[1][0].v = *reinterpret_cast<const float4*>(xp + 16 * DK + kt);
        ar[1][1].v = *reinterpret_cast<const float4*>(xp + 24 * DK + kt);
        F4 bh[4], bl[4];
#pragma unroll
        for (int nt = 0; nt < 4; nt++) {
            bh[nt].v = *reinterpret_cast<const float4*>(bhp + (size_t)nt * 8 * DK + kt);
            bl[nt].v = *reinterpret_cast<const float4*>(blp + (size_t)nt * 8 * DK + kt);
        }

        // ---- split A into tf32 hi/lo (exact truncation split) ----
        F4 ah[2][2], al[2][2];
#pragma unroll
        for (int mt = 0; mt < 2; mt++)
#pragma unroll
            for (int h = 0; h < 2; h++)
#pragma unroll
                for (int c = 0; c < 4; c++) {
                    float v  = ar[mt][h].f[c];
                    float hi = tf32_trunc(v);
                    ah[mt][h].f[c] = hi;
                    al[mt][h].f[c] = tf32_trunc(v - hi);
                }

        // ---- two k=8 MMA steps per 16-group (permuted k mapping) ----
#pragma unroll
        for (int s = 0; s < 2; s++) {
            const int c0 = 2 * s, c1 = 2 * s + 1;
            uint32_t afh[2][4], afl[2][4];
#pragma unroll
            for (int mt = 0; mt < 2; mt++) {
                afh[mt][0] = ah[mt][0].u[c0];  afh[mt][1] = ah[mt][1].u[c0];
                afh[mt][2] = ah[mt][0].u[c1];  afh[mt][3] = ah[mt][1].u[c1];
                afl[mt][0] = al[mt][0].u[c0];  afl[mt][1] = al[mt][1].u[c0];
                afl[mt][2] = al[mt][0].u[c1];  afl[mt][3] = al[mt][1].u[c1];
            }
#pragma unroll
            for (int nt = 0; nt < 4; nt++) {
                const uint32_t bh0 = bh[nt].u[c0], bh1 = bh[nt].u[c1];
                const uint32_t bl0 = bl[nt].u[c0], bl1 = bl[nt].u[c1];
#pragma unroll
                for (int mt = 0; mt < 2; mt++) {
                    mma8(acc[mt][nt], afh[mt], bh0, bh1);   // hi*hi
                    mma8(acc[mt][nt], afh[mt], bl0, bl1);   // hi*lo
                    mma8(acc[mt][nt], afl[mt], bh0, bh1);   // lo*hi
                }
            }
        }
    }

    // ---- epilogue: accumulators -> smem logits ----
#pragma unroll
    for (int mt = 0; mt < 2; mt++)
#pragma unroll
        for (int nt = 0; nt < 4; nt++) {
            const int r = tslice * 32 + mt * 16 + gid;
            const int e = eslice * 32 + nt * 8 + 2 * tig;
            lg[r][e]         = acc[mt][nt][0];
            lg[r][e + 1]     = acc[mt][nt][1];
            lg[r + 8][e]     = acc[mt][nt][2];
            lg[r + 8][e + 1] = acc[mt][nt][3];
        }
    __syncthreads();

    float* out_gates = out;
    float* out_idx   = out + 2 * NTOK;
    float* out_load  = out + 4 * NTOK;
    float* out_tlog  = out + 4 * NTOK + NE;

    if (tid < BM) {
        const float* row = lg[tid];
        // jax.lax.top_k tie-break: lowest index wins -> strict '>' ascending scan
        float m1 = -1e30f, m2 = -1e30f;
        int   i1 = 0,      i2 = 0;
#pragma unroll 8
        for (int e = 0; e < NE; e++) {
            float v = row[e];
            if (v > m1)      { m2 = m1; i2 = i1; m1 = v; i1 = e; }
            else if (v > m2) { m2 = v;  i2 = e; }
        }
        float ex  = expf(m2 - m1);      // stable: m1 >= m2
        float inv = 1.0f / (1.0f + ex);
        float g1  = inv;
        float g2  = ex * inv;

        const int t = tok0 + tid;
        reinterpret_cast<float2*>(out_gates)[t] = make_float2(g1, g2);
        reinterpret_cast<float2*>(out_idx)[t]   = make_float2((float)i1, (float)i2);
        reinterpret_cast<float2*>(out_tlog)[t]  = make_float2(m1, m2);

        sg[2 * tid] = g1;  sg[2 * tid + 1] = g2;
        si[2 * tid] = i1;  si[2 * tid + 1] = i2;
    }
    __syncthreads();

    // per-CTA deterministic expert-load partial, one atomic per expert per CTA
    if (tid < NE) {
        float ssum = 0.0f;
#pragma unroll 8
        for (int n = 0; n < 2 * BM; n++)
            ssum += (si[n] == tid) ? sg[n] : 0.0f;
        atomicAdd(out_load + tid, ssum);
    }
}

// ---------------------------------------------------------------------------
extern "C" void kernel_launch(void* const* d_in, const int* in_sizes, int n_in,
                              void* d_out, int out_size) {
    const float* x = (const float*)d_in[0];   // [32768, 2048]
    const float* w = (const float*)d_in[1];   // [64, 2048]
    float* out = (float*)d_out;

    prep_kernel<<<(NE * DK) / 256, 256>>>(w);          // split gate_w -> hi/lo
    zero_load_kernel<<<1, NE>>>(out + 4 * NTOK);       // load region (d_out poisoned)
    router_kernel<<<NTOK / BM, NTHREADS>>>(x, out);
}

// round 4
// speedup vs baseline: 1.8913x; 1.4545x over previous
#include <cuda_runtime.h>
#include <cuda_fp16.h>
#include <cstdint>

// ---------------------------------------------------------------------------
// ModalityRouter via mma.sync m16n8k16.f16 with 2-limb fp32 split (3 products)
//   logits = x @ gate_w^T ; top-2 ; softmax ; expert load
//   x: [32768, 2048] fp32   gate_w: [64, 2048] fp32
// Output fp32: gates[65536] | idx[65536] | load[64] | top_logits[65536]
// ---------------------------------------------------------------------------

#define DK        2048
#define NE        64
#define NTOK      32768
#define BM        128
#define NTHREADS  256
#define NGROUPS   (DK / 16)      // 128 groups of 16 k-columns

// precomputed fp16 limb split of gate_w: w = B0 + B1 (row-major [expert][k])
__device__ __half g_B0[NE * DK];
__device__ __half g_B1[NE * DK];

__global__ void prep_kernel(const float* __restrict__ w) {
    int i = blockIdx.x * 256 + threadIdx.x;        // grid covers NE*DK/4
    float4 v = reinterpret_cast<const float4*>(w)[i];
    __half h0x = __float2half_rn(v.x), h0y = __float2half_rn(v.y);
    __half h0z = __float2half_rn(v.z), h0w = __float2half_rn(v.w);
    __half h1x = __float2half_rn(v.x - __half2float(h0x));
    __half h1y = __float2half_rn(v.y - __half2float(h0y));
    __half h1z = __float2half_rn(v.z - __half2float(h0z));
    __half h1w = __float2half_rn(v.w - __half2float(h0w));
    __half2* b0 = reinterpret_cast<__half2*>(g_B0 + 4 * i);
    __half2* b1 = reinterpret_cast<__half2*>(g_B1 + 4 * i);
    b0[0] = __halves2half2(h0x, h0y);  b0[1] = __halves2half2(h0z, h0w);
    b1[0] = __halves2half2(h1x, h1y);  b1[1] = __halves2half2(h1z, h1w);
}

__global__ void zero_load_kernel(float* __restrict__ p) { p[threadIdx.x] = 0.0f; }

// warp-level tensor op: D += A(f16) * B(f16), f32 accumulate
__device__ __forceinline__ void mma16(float* d, const uint32_t* a,
                                      uint32_t b0, uint32_t b1) {
    asm volatile(
        "mma.sync.aligned.m16n8k16.row.col.f32.f16.f16.f32 "
        "{%0,%1,%2,%3}, {%4,%5,%6,%7}, {%8,%9}, {%0,%1,%2,%3};"
        : "+f"(d[0]), "+f"(d[1]), "+f"(d[2]), "+f"(d[3])
        : "r"(a[0]), "r"(a[1]), "r"(a[2]), "r"(a[3]), "r"(b0), "r"(b1));
}

// split a float2 into (hi half2, lo half2)
__device__ __forceinline__ void split2(float2 f, uint32_t& hi, uint32_t& lo) {
    __half2 h = __float22half2_rn(f);
    float2 hf = __half22float2(h);
    __half2 l = __float22half2_rn(make_float2(f.x - hf.x, f.y - hf.y));
    hi = *reinterpret_cast<uint32_t*>(&h);
    lo = *reinterpret_cast<uint32_t*>(&l);
}

// ---------------------------------------------------------------------------
__global__ void __launch_bounds__(NTHREADS, 2)
router_kernel(const float* __restrict__ x, float* __restrict__ out)
{
    __shared__ float lg[BM][NE + 1];
    __shared__ float sg[2 * BM];
    __shared__ int   si[2 * BM];

    const int tid    = threadIdx.x;
    const int wid    = tid >> 5;
    const int lane   = tid & 31;
    const int gid    = lane >> 2;       // fragment row/col group (0..7)
    const int tig    = lane & 3;        // thread-in-group (0..3)
    const int tslice = wid >> 1;        // token slice (0..3): 32 tokens each
    const int eslice = wid & 1;         // expert slice (0..1): 32 experts each
    const int tok0   = blockIdx.x * BM;

    // k-permutation (shared by A and B): physical 4t..4t+3 <-> logical
    // {2t, 2t+1, 2t+8, 2t+9}. One float4 per A fragment row, LDG.64 per B frag.
    const float* xp = x + (size_t)(tok0 + tslice * 32 + gid) * DK + tig * 4;
    const size_t boff = (size_t)(eslice * 32 + gid) * DK + tig * 4;
    const __half* b0p = g_B0 + boff;
    const __half* b1p = g_B1 + boff;

    float acc[2][4][4];
#pragma unroll
    for (int mt = 0; mt < 2; mt++)
#pragma unroll
        for (int nt = 0; nt < 4; nt++)
#pragma unroll
            for (int q = 0; q < 4; q++) acc[mt][nt][q] = 0.0f;

    for (int g = 0; g < NGROUPS; ++g) {
        const int kt = g * 16;

        // ---- loads ----
        float4 ar[2][2];  // [m-tile][row-half: gid / gid+8]
        ar[0][0] = *reinterpret_cast<const float4*>(xp + kt);
        ar[0][1] = *reinterpret_cast<const float4*>(xp + 8 * DK + kt);
        ar[1][0] = *reinterpret_cast<const float4*>(xp + 16 * DK + kt);
        ar[1][1] = *reinterpret_cast<const float4*>(xp + 24 * DK + kt);
        uint2 bh[4], bl[4];
#pragma unroll
        for (int nt = 0; nt < 4; nt++) {
            bh[nt] = *reinterpret_cast<const uint2*>(b0p + (size_t)nt * 8 * DK + kt);
            bl[nt] = *reinterpret_cast<const uint2*>(b1p + (size_t)nt * 8 * DK + kt);
        }

        // ---- split A into fp16 hi/lo fragments ----
        // A reg order: a0=(row g, k-lo) a1=(row g+8, k-lo) a2=(row g, k-hi) a3=(row g+8, k-hi)
        uint32_t ah[2][4], al[2][4];
#pragma unroll
        for (int mt = 0; mt < 2; mt++) {
            split2(make_float2(ar[mt][0].x, ar[mt][0].y), ah[mt][0], al[mt][0]);
            split2(make_float2(ar[mt][1].x, ar[mt][1].y), ah[mt][1], al[mt][1]);
            split2(make_float2(ar[mt][0].z, ar[mt][0].w), ah[mt][2], al[mt][2]);
            split2(make_float2(ar[mt][1].z, ar[mt][1].w), ah[mt][3], al[mt][3]);
        }

        // ---- 3 products per tile: hi*hi + hi*lo + lo*hi ----
#pragma unroll
        for (int nt = 0; nt < 4; nt++) {
#pragma unroll
            for (int mt = 0; mt < 2; mt++) {
                mma16(acc[mt][nt], ah[mt], bh[nt].x, bh[nt].y);   // hi*hi
                mma16(acc[mt][nt], ah[mt], bl[nt].x, bl[nt].y);   // hi*lo
                mma16(acc[mt][nt], al[mt], bh[nt].x, bh[nt].y);   // lo*hi
            }
        }
    }

    // ---- epilogue: accumulators -> smem logits ----
#pragma unroll
    for (int mt = 0; mt < 2; mt++)
#pragma unroll
        for (int nt = 0; nt < 4; nt++) {
            const int r = tslice * 32 + mt * 16 + gid;
            const int e = eslice * 32 + nt * 8 + 2 * tig;
            lg[r][e]         = acc[mt][nt][0];
            lg[r][e + 1]     = acc[mt][nt][1];
            lg[r + 8][e]     = acc[mt][nt][2];
            lg[r + 8][e + 1] = acc[mt][nt][3];
        }
    __syncthreads();

    float* out_gates = out;
    float* out_idx   = out + 2 * NTOK;
    float* out_load  = out + 4 * NTOK;
    float* out_tlog  = out + 4 * NTOK + NE;

    if (tid < BM) {
        const float* row = lg[tid];
        // jax.lax.top_k tie-break: lowest index wins -> strict '>' ascending scan
        float m1 = -1e30f, m2 = -1e30f;
        int   i1 = 0,      i2 = 0;
#pragma unroll 8
        for (int e = 0; e < NE; e++) {
            float v = row[e];
            if (v > m1)      { m2 = m1; i2 = i1; m1 = v; i1 = e; }
            else if (v > m2) { m2 = v;  i2 = e; }
        }
        float ex  = expf(m2 - m1);      // stable: m1 >= m2
        float inv = 1.0f / (1.0f + ex);
        float g1  = inv;
        float g2  = ex * inv;

        const int t = tok0 + tid;
        reinterpret_cast<float2*>(out_gates)[t] = make_float2(g1, g2);
        reinterpret_cast<float2*>(out_idx)[t]   = make_float2((float)i1, (float)i2);
        reinterpret_cast<float2*>(out_tlog)[t]  = make_float2(m1, m2);

        sg[2 * tid] = g1;  sg[2 * tid + 1] = g2;
        si[2 * tid] = i1;  si[2 * tid + 1] = i2;
    }
    __syncthreads();

    // per-CTA deterministic expert-load partial, one atomic per expert per CTA
    if (tid < NE) {
        float ssum = 0.0f;
#pragma unroll 8
        for (int n = 0; n < 2 * BM; n++)
            ssum += (si[n] == tid) ? sg[n] : 0.0f;
        atomicAdd(out_load + tid, ssum);
    }
}

// ---------------------------------------------------------------------------
extern "C" void kernel_launch(void* const* d_in, const int* in_sizes, int n_in,
                              void* d_out, int out_size) {
    const float* x = (const float*)d_in[0];   // [32768, 2048]
    const float* w = (const float*)d_in[1];   // [64, 2048]
    float* out = (float*)d_out;

    prep_kernel<<<(NE * DK) / (4 * 256), 256>>>(w);    // split gate_w -> fp16 limbs
    zero_load_kernel<<<1, NE>>>(out + 4 * NTOK);       // load region (d_out poisoned)
    router_kernel<<<NTOK / BM, NTHREADS>>>(x, out);
}

// round 5
// speedup vs baseline: 1.9261x; 1.0184x over previous
#include <cuda_runtime.h>
#include <cuda_fp16.h>
#include <cstdint>

// ---------------------------------------------------------------------------
// ModalityRouter via mma.sync m16n8k16.f16 with 2-limb fp32 split (3 products)
// Software-pipelined: A/B global loads double-buffered one k-group ahead.
//   logits = x @ gate_w^T ; top-2 ; softmax ; expert load
//   x: [32768, 2048] fp32   gate_w: [64, 2048] fp32
// Output fp32: gates[65536] | idx[65536] | load[64] | top_logits[65536]
// ---------------------------------------------------------------------------

#define DK        2048
#define NE        64
#define NTOK      32768
#define BM        128
#define NTHREADS  256
#define NGROUPS   (DK / 16)      // 128 groups of 16 k-columns

// precomputed fp16 limb split of gate_w: w = B0 + B1 (row-major [expert][k])
__device__ __half g_B0[NE * DK];
__device__ __half g_B1[NE * DK];

__global__ void prep_kernel(const float* __restrict__ w, float* __restrict__ out_load) {
    int i = blockIdx.x * 256 + threadIdx.x;        // grid covers NE*DK/4
    // fold in zeroing of the expert-load output region (d_out is poisoned)
    if (blockIdx.x == 0 && threadIdx.x < NE) out_load[threadIdx.x] = 0.0f;
    float4 v = reinterpret_cast<const float4*>(w)[i];
    __half h0x = __float2half_rn(v.x), h0y = __float2half_rn(v.y);
    __half h0z = __float2half_rn(v.z), h0w = __float2half_rn(v.w);
    __half h1x = __float2half_rn(v.x - __half2float(h0x));
    __half h1y = __float2half_rn(v.y - __half2float(h0y));
    __half h1z = __float2half_rn(v.z - __half2float(h0z));
    __half h1w = __float2half_rn(v.w - __half2float(h0w));
    __half2* b0 = reinterpret_cast<__half2*>(g_B0 + 4 * i);
    __half2* b1 = reinterpret_cast<__half2*>(g_B1 + 4 * i);
    b0[0] = __halves2half2(h0x, h0y);  b0[1] = __halves2half2(h0z, h0w);
    b1[0] = __halves2half2(h1x, h1y);  b1[1] = __halves2half2(h1z, h1w);
}

// warp-level tensor op: D += A(f16) * B(f16), f32 accumulate
__device__ __forceinline__ void mma16(float* d, const uint32_t* a,
                                      uint32_t b0, uint32_t b1) {
    asm volatile(
        "mma.sync.aligned.m16n8k16.row.col.f32.f16.f16.f32 "
        "{%0,%1,%2,%3}, {%4,%5,%6,%7}, {%8,%9}, {%0,%1,%2,%3};"
        : "+f"(d[0]), "+f"(d[1]), "+f"(d[2]), "+f"(d[3])
        : "r"(a[0]), "r"(a[1]), "r"(a[2]), "r"(a[3]), "r"(b0), "r"(b1));
}

// split a float2 into (hi half2, lo half2)
__device__ __forceinline__ void split2(float2 f, uint32_t& hi, uint32_t& lo) {
    __half2 h = __float22half2_rn(f);
    float2 hf = __half22float2(h);
    __half2 l = __float22half2_rn(make_float2(f.x - hf.x, f.y - hf.y));
    hi = *reinterpret_cast<uint32_t*>(&h);
    lo = *reinterpret_cast<uint32_t*>(&l);
}

// ---------------------------------------------------------------------------
__global__ void __launch_bounds__(NTHREADS, 2)
router_kernel(const float* __restrict__ x, float* __restrict__ out)
{
    __shared__ float lg[BM][NE + 1];
    __shared__ float sg[2 * BM];
    __shared__ int   si[2 * BM];

    const int tid    = threadIdx.x;
    const int wid    = tid >> 5;
    const int lane   = tid & 31;
    const int gid    = lane >> 2;       // fragment row/col group (0..7)
    const int tig    = lane & 3;        // thread-in-group (0..3)
    const int tslice = wid >> 1;        // token slice (0..3): 32 tokens each
    const int eslice = wid & 1;         // expert slice (0..1): 32 experts each
    const int tok0   = blockIdx.x * BM;

    // k-permutation (shared by A and B): physical 4t..4t+3 <-> logical
    // {2t, 2t+1, 2t+8, 2t+9}. One float4 per A fragment row, LDG.64 per B frag.
    const float* xp = x + (size_t)(tok0 + tslice * 32 + gid) * DK + tig * 4;
    const size_t boff = (size_t)(eslice * 32 + gid) * DK + tig * 4;
    const __half* b0p = g_B0 + boff;
    const __half* b1p = g_B1 + boff;

    float acc[2][4][4];
#pragma unroll
    for (int mt = 0; mt < 2; mt++)
#pragma unroll
        for (int nt = 0; nt < 4; nt++)
#pragma unroll
            for (int q = 0; q < 4; q++) acc[mt][nt][q] = 0.0f;

    // double buffers: A raw fp32 fragments, B fp16 limb fragments
    float4 abuf[2][2][2];     // [buf][m-tile][row-half]
    uint2  bhb[2][4], blb[2][4];

    // prologue: group 0 -> buffer 0
#pragma unroll
    for (int mt = 0; mt < 2; mt++) {
        abuf[0][mt][0] = *reinterpret_cast<const float4*>(xp + (mt * 16 + 0) * DK);
        abuf[0][mt][1] = *reinterpret_cast<const float4*>(xp + (mt * 16 + 8) * DK);
    }
#pragma unroll
    for (int nt = 0; nt < 4; nt++) {
        bhb[0][nt] = *reinterpret_cast<const uint2*>(b0p + (size_t)nt * 8 * DK);
        blb[0][nt] = *reinterpret_cast<const uint2*>(b1p + (size_t)nt * 8 * DK);
    }

#pragma unroll 2
    for (int g = 0; g < NGROUPS; ++g) {
        const int cur = g & 1;
        const int nxt = cur ^ 1;

        // ---- prefetch group g+1 into the other buffer ----
        if (g + 1 < NGROUPS) {
            const int kt = (g + 1) * 16;
#pragma unroll
            for (int mt = 0; mt < 2; mt++) {
                abuf[nxt][mt][0] = *reinterpret_cast<const float4*>(xp + (mt * 16 + 0) * DK + kt);
                abuf[nxt][mt][1] = *reinterpret_cast<const float4*>(xp + (mt * 16 + 8) * DK + kt);
            }
#pragma unroll
            for (int nt = 0; nt < 4; nt++) {
                bhb[nxt][nt] = *reinterpret_cast<const uint2*>(b0p + (size_t)nt * 8 * DK + kt);
                blb[nxt][nt] = *reinterpret_cast<const uint2*>(b1p + (size_t)nt * 8 * DK + kt);
            }
        }

        // ---- split A into fp16 hi/lo fragments ----
        // A reg order: a0=(row g, k-lo) a1=(row g+8, k-lo) a2=(row g, k-hi) a3=(row g+8, k-hi)
        uint32_t ah[2][4], al[2][4];
#pragma unroll
        for (int mt = 0; mt < 2; mt++) {
            split2(make_float2(abuf[cur][mt][0].x, abuf[cur][mt][0].y), ah[mt][0], al[mt][0]);
            split2(make_float2(abuf[cur][mt][1].x, abuf[cur][mt][1].y), ah[mt][1], al[mt][1]);
            split2(make_float2(abuf[cur][mt][0].z, abuf[cur][mt][0].w), ah[mt][2], al[mt][2]);
            split2(make_float2(abuf[cur][mt][1].z, abuf[cur][mt][1].w), ah[mt][3], al[mt][3]);
        }

        // ---- 3 products per tile: hi*hi + hi*lo + lo*hi ----
#pragma unroll
        for (int nt = 0; nt < 4; nt++) {
#pragma unroll
            for (int mt = 0; mt < 2; mt++) {
                mma16(acc[mt][nt], ah[mt], bhb[cur][nt].x, bhb[cur][nt].y);   // hi*hi
                mma16(acc[mt][nt], ah[mt], blb[cur][nt].x, blb[cur][nt].y);   // hi*lo
                mma16(acc[mt][nt], al[mt], bhb[cur][nt].x, bhb[cur][nt].y);   // lo*hi
            }
        }
    }

    // ---- epilogue: accumulators -> smem logits ----
#pragma unroll
    for (int mt = 0; mt < 2; mt++)
#pragma unroll
        for (int nt = 0; nt < 4; nt++) {
            const int r = tslice * 32 + mt * 16 + gid;
            const int e = eslice * 32 + nt * 8 + 2 * tig;
            lg[r][e]         = acc[mt][nt][0];
            lg[r][e + 1]     = acc[mt][nt][1];
            lg[r + 8][e]     = acc[mt][nt][2];
            lg[r + 8][e + 1] = acc[mt][nt][3];
        }
    __syncthreads();

    float* out_gates = out;
    float* out_idx   = out + 2 * NTOK;
    float* out_load  = out + 4 * NTOK;
    float* out_tlog  = out + 4 * NTOK + NE;

    if (tid < BM) {
        const float* row = lg[tid];
        // jax.lax.top_k tie-break: lowest index wins -> strict '>' ascending scan
        float m1 = -1e30f, m2 = -1e30f;
        int   i1 = 0,      i2 = 0;
#pragma unroll 8
        for (int e = 0; e < NE; e++) {
            float v = row[e];
            if (v > m1)      { m2 = m1; i2 = i1; m1 = v; i1 = e; }
            else if (v > m2) { m2 = v;  i2 = e; }
        }
        float ex  = expf(m2 - m1);      // stable: m1 >= m2
        float inv = 1.0f / (1.0f + ex);
        float g1  = inv;
        float g2  = ex * inv;

        const int t = tok0 + tid;
        reinterpret_cast<float2*>(out_gates)[t] = make_float2(g1, g2);
        reinterpret_cast<float2*>(out_idx)[t]   = make_float2((float)i1, (float)i2);
        reinterpret_cast<float2*>(out_tlog)[t]  = make_float2(m1, m2);

        sg[2 * tid] = g1;  sg[2 * tid + 1] = g2;
        si[2 * tid] = i1;  si[2 * tid + 1] = i2;
    }
    __syncthreads();

    // per-CTA deterministic expert-load partial, one atomic per expert per CTA
    if (tid < NE) {
        float ssum = 0.0f;
#pragma unroll 8
        for (int n = 0; n < 2 * BM; n++)
            ssum += (si[n] == tid) ? sg[n] : 0.0f;
        atomicAdd(out_load + tid, ssum);
    }
}

// ---------------------------------------------------------------------------
extern "C" void kernel_launch(void* const* d_in, const int* in_sizes, int n_in,
                              void* d_out, int out_size) {
    const float* x = (const float*)d_in[0];   // [32768, 2048]
    const float* w = (const float*)d_in[1];   // [64, 2048]
    float* out = (float*)d_out;

    prep_kernel<<<(NE * DK) / (4 * 256), 256>>>(w, out + 4 * NTOK);
    router_kernel<<<NTOK / BM, NTHREADS>>>(x, out);
}

// round 6
// speedup vs baseline: 2.4683x; 1.2815x over previous
#include <cuda_runtime.h>
#include <cuda_fp16.h>
#include <cstdint>

// ---------------------------------------------------------------------------
// ModalityRouter via mma.sync m16n8k16.f16 with 2-limb fp32 split (3 products)
// B stored FRAGMENT-MAJOR: one coalesced LDG.128 yields both limb fragments.
//   logits = x @ gate_w^T ; top-2 ; softmax ; expert load
//   x: [32768, 2048] fp32   gate_w: [64, 2048] fp32
// Output fp32: gates[65536] | idx[65536] | load[64] | top_logits[65536]
// ---------------------------------------------------------------------------

#define DK        2048
#define NE        64
#define NTOK      32768
#define BM        128
#define NTHREADS  256
#define NGROUPS   (DK / 16)      // 128 groups of 16 k-columns

// fragment-major fp16 limb split of gate_w:
//   g_Bfrag[((es*NGROUPS + g)*4 + nt)*32 + lane] = {hi.x, hi.y, lo.x, lo.y}
//   where lane=(gid*4+tig) holds halves k = g*16 + tig*4 .. +3 of expert
//   e = es*32 + nt*8 + gid   (same k-permutation as the A fragments)
__device__ uint4 g_Bfrag[2 * NGROUPS * 4 * 32];     // 512 KB

__device__ __forceinline__ uint32_t pack_h2(float a, float b) {
    __half2 h = __halves2half2(__float2half_rn(a), __float2half_rn(b));
    return *reinterpret_cast<uint32_t*>(&h);
}

__global__ void prep_kernel(const float* __restrict__ w, float* __restrict__ out_load) {
    const int t = blockIdx.x * 256 + threadIdx.x;    // 32768 threads total
    if (blockIdx.x == 0 && threadIdx.x < NE) out_load[threadIdx.x] = 0.0f;

    const int lane = t & 31;
    const int nt   = (t >> 5) & 3;
    const int g    = (t >> 7) & (NGROUPS - 1);
    const int es   = t >> 14;
    const int gid  = lane >> 2;
    const int tig  = lane & 3;
    const int e    = es * 32 + nt * 8 + gid;
    const int kb   = g * 16 + tig * 4;

    float4 v = *reinterpret_cast<const float4*>(w + (size_t)e * DK + kb);
    float hx = __half2float(__float2half_rn(v.x));
    float hy = __half2float(__float2half_rn(v.y));
    float hz = __half2float(__float2half_rn(v.z));
    float hw = __half2float(__float2half_rn(v.w));

    uint4 frag;
    frag.x = pack_h2(v.x, v.y);                 // hi limb, k {4t, 4t+1}
    frag.y = pack_h2(v.z, v.w);                 // hi limb, k {4t+2, 4t+3}
    frag.z = pack_h2(v.x - hx, v.y - hy);       // lo limb
    frag.w = pack_h2(v.z - hz, v.w - hw);
    g_Bfrag[t] = frag;
}

// warp-level tensor op: D += A(f16) * B(f16), f32 accumulate
__device__ __forceinline__ void mma16(float* d, const uint32_t* a,
                                      uint32_t b0, uint32_t b1) {
    asm volatile(
        "mma.sync.aligned.m16n8k16.row.col.f32.f16.f16.f32 "
        "{%0,%1,%2,%3}, {%4,%5,%6,%7}, {%8,%9}, {%0,%1,%2,%3};"
        : "+f"(d[0]), "+f"(d[1]), "+f"(d[2]), "+f"(d[3])
        : "r"(a[0]), "r"(a[1]), "r"(a[2]), "r"(a[3]), "r"(b0), "r"(b1));
}

// split a float2 into (hi half2, lo half2)
__device__ __forceinline__ void split2(float2 f, uint32_t& hi, uint32_t& lo) {
    __half2 h = __float22half2_rn(f);
    float2 hf = __half22float2(h);
    __half2 l = __float22half2_rn(make_float2(f.x - hf.x, f.y - hf.y));
    hi = *reinterpret_cast<uint32_t*>(&h);
    lo = *reinterpret_cast<uint32_t*>(&l);
}

// ---------------------------------------------------------------------------
__global__ void __launch_bounds__(NTHREADS, 2)
router_kernel(const float* __restrict__ x, float* __restrict__ out)
{
    __shared__ float lg[BM][NE + 1];
    __shared__ float sg[2 * BM];
    __shared__ int   si[2 * BM];

    const int tid    = threadIdx.x;
    const int wid    = tid >> 5;
    const int lane   = tid & 31;
    const int gid    = lane >> 2;       // fragment row/col group (0..7)
    const int tig    = lane & 3;        // thread-in-group (0..3)
    const int tslice = wid >> 1;        // token slice (0..3): 32 tokens each
    const int eslice = wid & 1;         // expert slice (0..1): 32 experts each
    const int tok0   = blockIdx.x * BM;

    // A pointer (k-permutation {2t,2t+1,2t+8,2t+9} <-> physical 4t..4t+3,
    // shared by A and B fragments so the dot product is order-invariant)
    const float* xp = x + (size_t)(tok0 + tslice * 32 + gid) * DK + tig * 4;
    // B fragment-major pointer: per group stride = 4 ntiles * 32 lanes
    const uint4* bfp = g_Bfrag + (size_t)eslice * NGROUPS * 4 * 32 + lane;

    float acc[2][4][4];
#pragma unroll
    for (int mt = 0; mt < 2; mt++)
#pragma unroll
        for (int nt = 0; nt < 4; nt++)
#pragma unroll
            for (int q = 0; q < 4; q++) acc[mt][nt][q] = 0.0f;

    // double buffers
    float4 abuf[2][2][2];     // [buf][m-tile][row-half]
    uint4  bbuf[2][4];        // [buf][ntile]

    // prologue: group 0 -> buffer 0
#pragma unroll
    for (int mt = 0; mt < 2; mt++) {
        abuf[0][mt][0] = *reinterpret_cast<const float4*>(xp + (mt * 16 + 0) * DK);
        abuf[0][mt][1] = *reinterpret_cast<const float4*>(xp + (mt * 16 + 8) * DK);
    }
#pragma unroll
    for (int nt = 0; nt < 4; nt++)
        bbuf[0][nt] = bfp[nt * 32];

#pragma unroll 2
    for (int g = 0; g < NGROUPS; ++g) {
        const int cur = g & 1;
        const int nxt = cur ^ 1;

        // ---- prefetch group g+1 into the other buffer ----
        if (g + 1 < NGROUPS) {
            const int kt = (g + 1) * 16;
#pragma unroll
            for (int mt = 0; mt < 2; mt++) {
                abuf[nxt][mt][0] = *reinterpret_cast<const float4*>(xp + (mt * 16 + 0) * DK + kt);
                abuf[nxt][mt][1] = *reinterpret_cast<const float4*>(xp + (mt * 16 + 8) * DK + kt);
            }
            const uint4* bg = bfp + (size_t)(g + 1) * 128;
#pragma unroll
            for (int nt = 0; nt < 4; nt++)
                bbuf[nxt][nt] = bg[nt * 32];
        }

        // ---- split A into fp16 hi/lo fragments ----
        uint32_t ah[2][4], al[2][4];
#pragma unroll
        for (int mt = 0; mt < 2; mt++) {
            split2(make_float2(abuf[cur][mt][0].x, abuf[cur][mt][0].y), ah[mt][0], al[mt][0]);
            split2(make_float2(abuf[cur][mt][1].x, abuf[cur][mt][1].y), ah[mt][1], al[mt][1]);
            split2(make_float2(abuf[cur][mt][0].z, abuf[cur][mt][0].w), ah[mt][2], al[mt][2]);
            split2(make_float2(abuf[cur][mt][1].z, abuf[cur][mt][1].w), ah[mt][3], al[mt][3]);
        }

        // ---- 3 products per tile: hi*hi + hi*lo + lo*hi ----
#pragma unroll
        for (int nt = 0; nt < 4; nt++) {
            const uint4 b = bbuf[cur][nt];
#pragma unroll
            for (int mt = 0; mt < 2; mt++) {
                mma16(acc[mt][nt], ah[mt], b.x, b.y);   // hi*hi
                mma16(acc[mt][nt], ah[mt], b.z, b.w);   // hi*lo
                mma16(acc[mt][nt], al[mt], b.x, b.y);   // lo*hi
            }
        }
    }

    // ---- epilogue: accumulators -> smem logits ----
#pragma unroll
    for (int mt = 0; mt < 2; mt++)
#pragma unroll
        for (int nt = 0; nt < 4; nt++) {
            const int r = tslice * 32 + mt * 16 + gid;
            const int e = eslice * 32 + nt * 8 + 2 * tig;
            lg[r][e]         = acc[mt][nt][0];
            lg[r][e + 1]     = acc[mt][nt][1];
            lg[r + 8][e]     = acc[mt][nt][2];
            lg[r + 8][e + 1] = acc[mt][nt][3];
        }
    __syncthreads();

    float* out_gates = out;
    float* out_idx   = out + 2 * NTOK;
    float* out_load  = out + 4 * NTOK;
    float* out_tlog  = out + 4 * NTOK + NE;

    if (tid < BM) {
        const float* row = lg[tid];
        // jax.lax.top_k tie-break: lowest index wins -> strict '>' ascending scan
        float m1 = -1e30f, m2 = -1e30f;
        int   i1 = 0,      i2 = 0;
#pragma unroll 8
        for (int e = 0; e < NE; e++) {
            float v = row[e];
            if (v > m1)      { m2 = m1; i2 = i1; m1 = v; i1 = e; }
            else if (v > m2) { m2 = v;  i2 = e; }
        }
        float ex  = expf(m2 - m1);      // stable: m1 >= m2
        float inv = 1.0f / (1.0f + ex);
        float g1  = inv;
        float g2  = ex * inv;

        const int t = tok0 + tid;
        reinterpret_cast<float2*>(out_gates)[t] = make_float2(g1, g2);
        reinterpret_cast<float2*>(out_idx)[t]   = make_float2((float)i1, (float)i2);
        reinterpret_cast<float2*>(out_tlog)[t]  = make_float2(m1, m2);

        sg[2 * tid] = g1;  sg[2 * tid + 1] = g2;
        si[2 * tid] = i1;  si[2 * tid + 1] = i2;
    }
    __syncthreads();

    // per-CTA deterministic expert-load partial, one atomic per expert per CTA
    if (tid < NE) {
        float ssum = 0.0f;
#pragma unroll 8
        for (int n = 0; n < 2 * BM; n++)
            ssum += (si[n] == tid) ? sg[n] : 0.0f;
        atomicAdd(out_load + tid, ssum);
    }
}

// ---------------------------------------------------------------------------
extern "C" void kernel_launch(void* const* d_in, const int* in_sizes, int n_in,
                              void* d_out, int out_size) {
    const float* x = (const float*)d_in[0];   // [32768, 2048]
    const float* w = (const float*)d_in[1];   // [64, 2048]
    float* out = (float*)d_out;

    prep_kernel<<<128, 256>>>(w, out + 4 * NTOK);      // frag-major B limbs + zero load
    router_kernel<<<NTOK / BM, NTHREADS>>>(x, out);
}